// round 11
// baseline (speedup 1.0000x reference)
#include <cuda_runtime.h>
#include <cuda_bf16.h>

// Problem constants (fixed by the dataset)
#define B_TOT   1024
#define S_LEN   2048
#define F_IN    9
#define NOUT    8
#define UDIM    256
#define LBK     3
#define DDIM    11      // NOUT + 3
#define XDIM    33      // LBK * DDIM
#define H1DIM   512     // 2*U
#define T_OUT   2044    // S - 1 - LBK
#define M_ROWS  8
#define NCTA    128     // NCTA * M_ROWS == B_TOT
#define NTHREADS 512    // 16 warps

__device__ __forceinline__ float tanh_fast(float x) {
    float y;
    asm("tanh.approx.f32 %0, %1;" : "=f"(y) : "f"(x));
    return y;
}

__global__ __launch_bounds__(NTHREADS, 1)
void dps_kernel(const float* __restrict__ inputs,
                const float* __restrict__ ln1_g, const float* __restrict__ ln1_b,
                const float* __restrict__ w1,    const float* __restrict__ b1,
                const float* __restrict__ w2,    const float* __restrict__ b2,
                const float* __restrict__ wu,    const float* __restrict__ bu,
                const float* __restrict__ ln2_g, const float* __restrict__ ln2_b,
                const float* __restrict__ wbeta,
                const float* __restrict__ wd1,   const float* __restrict__ bd1,
                const float* __restrict__ wd2,   const float* __restrict__ bd2,
                const int*   __restrict__ fix,
                float* __restrict__ out)
{
    __shared__ __align__(16) float s_xx [M_ROWS][36];      // post-LN1 x (rows 144B, 16B-aligned)
    __shared__ __align__(16) float s_big[M_ROWS][H1DIM];   // h1 (enc) then t1 (dec) - aliased
    __shared__ __align__(16) float s_h  [M_ROWS][UDIM];    // encoder output
    __shared__ __align__(16) float s_comb[M_ROWS][260];    // [0..255]=st (after LN2), [256]=ect
    __shared__ float s_win[M_ROWS][LBK][NOUT];
    __shared__ float s_y  [M_ROWS][NOUT];
    __shared__ float s_gp [M_ROWS][NOUT];                  // phase-G cross-half partials

    const int tid  = threadIdx.x;
    const int lane = tid & 31;
    const int wid  = tid >> 5;
    const int row0 = blockIdx.x * M_ROWS;

    const int fix0 = fix[0];
    const int fix1 = fix[1];

    // float4 views of the weight matrices (j-contiguous quads)
    const float4* w2v  = (const float4*)w2;    // [512][64]
    const float4* wuv  = (const float4*)wu;    // [256][64]
    const float4* wd1v = (const float4*)wd1;   // [257][128]

    // ---- init window: win[m][t][n] = inputs[row0+m, t, 1+n]
    for (int idx = tid; idx < M_ROWS * LBK * NOUT; idx += NTHREADS) {
        int m = idx / (LBK * NOUT);
        int r = idx % (LBK * NOUT);
        int t = r / NOUT, n = r % NOUT;
        s_win[m][t][n] = inputs[((size_t)(row0 + m) * S_LEN + t) * F_IN + 1 + n];
    }
    __syncthreads();

    for (int i = LBK; i < S_LEN - 1; ++i) {
        // ================= Phase A: build x (lc + win), LayerNorm1 =================
        if (tid < M_ROWS * LBK) {
            int m = tid / LBK, t = tid % LBK;
            int s = i - LBK + t;
            size_t base = ((size_t)(row0 + m) * S_LEN + s) * F_IN;
            float ld = inputs[base];
            float df = (s > 0) ? (ld - inputs[base - F_IN]) : 0.0f;
            float x[DDIM];
            x[0] = ld; x[1] = ld; x[2] = df;
            #pragma unroll
            for (int n = 0; n < NOUT; ++n) x[3 + n] = s_win[m][t][n];
            float mean = 0.f;
            #pragma unroll
            for (int d = 0; d < DDIM; ++d) mean += x[d];
            mean *= (1.0f / DDIM);
            float var = 0.f;
            #pragma unroll
            for (int d = 0; d < DDIM; ++d) { float c = x[d] - mean; var += c * c; }
            var *= (1.0f / DDIM);
            float rs = rsqrtf(var + 1e-3f);
            #pragma unroll
            for (int d = 0; d < DDIM; ++d)
                s_xx[m][t * DDIM + d] = (x[d] - mean) * rs * ln1_g[d] + ln1_b[d];
        }
        __syncthreads();

        // ================= Phase B: enc1 (33 -> 512) + tanh, one j per thread ======
        {
            float acc[M_ROWS];
            #pragma unroll
            for (int m = 0; m < M_ROWS; ++m) acc[m] = 0.f;
            const int j = tid;
            #pragma unroll 4
            for (int kk = 0; kk < 32; kk += 4) {
                float wv0 = w1[(kk + 0) * H1DIM + j];
                float wv1 = w1[(kk + 1) * H1DIM + j];
                float wv2 = w1[(kk + 2) * H1DIM + j];
                float wv3 = w1[(kk + 3) * H1DIM + j];
                #pragma unroll
                for (int m = 0; m < M_ROWS; ++m) {
                    float4 xv = *reinterpret_cast<const float4*>(&s_xx[m][kk]);
                    acc[m] = fmaf(xv.x, wv0, acc[m]);
                    acc[m] = fmaf(xv.y, wv1, acc[m]);
                    acc[m] = fmaf(xv.z, wv2, acc[m]);
                    acc[m] = fmaf(xv.w, wv3, acc[m]);
                }
            }
            {   // tail k = 32
                float wv = w1[32 * H1DIM + j];
                #pragma unroll
                for (int m = 0; m < M_ROWS; ++m)
                    acc[m] = fmaf(s_xx[m][32], wv, acc[m]);
            }
            float bb = b1[j];
            #pragma unroll
            for (int m = 0; m < M_ROWS; ++m)
                s_big[m][j] = tanh_fast(acc[m] + bb);
        }
        __syncthreads();

        // ===== Phase C: enc2 (512 -> 256), j-quads (LDG.128), 8-way k-split ========
        {
            const int q  = (wid << 2) | (lane & 3);   // 0..63 output quad (j = 4q..4q+3)
            const int sp = lane >> 2;                 // 0..7 split (lane bits 2..4)
            const int k0 = sp << 6;                   // 64 k per split
            float4 acc[M_ROWS];
            #pragma unroll
            for (int m = 0; m < M_ROWS; ++m) acc[m] = make_float4(0.f, 0.f, 0.f, 0.f);
            #pragma unroll 2
            for (int kk = k0; kk < k0 + 64; kk += 4) {
                float4 wq0 = w2v[(kk + 0) * 64 + q];
                float4 wq1 = w2v[(kk + 1) * 64 + q];
                float4 wq2 = w2v[(kk + 2) * 64 + q];
                float4 wq3 = w2v[(kk + 3) * 64 + q];
                #pragma unroll
                for (int m = 0; m < M_ROWS; ++m) {
                    float4 hv = *reinterpret_cast<const float4*>(&s_big[m][kk]);
                    acc[m].x = fmaf(hv.x, wq0.x, acc[m].x);
                    acc[m].y = fmaf(hv.x, wq0.y, acc[m].y);
                    acc[m].z = fmaf(hv.x, wq0.z, acc[m].z);
                    acc[m].w = fmaf(hv.x, wq0.w, acc[m].w);
                    acc[m].x = fmaf(hv.y, wq1.x, acc[m].x);
                    acc[m].y = fmaf(hv.y, wq1.y, acc[m].y);
                    acc[m].z = fmaf(hv.y, wq1.z, acc[m].z);
                    acc[m].w = fmaf(hv.y, wq1.w, acc[m].w);
                    acc[m].x = fmaf(hv.z, wq2.x, acc[m].x);
                    acc[m].y = fmaf(hv.z, wq2.y, acc[m].y);
                    acc[m].z = fmaf(hv.z, wq2.z, acc[m].z);
                    acc[m].w = fmaf(hv.z, wq2.w, acc[m].w);
                    acc[m].x = fmaf(hv.w, wq3.x, acc[m].x);
                    acc[m].y = fmaf(hv.w, wq3.y, acc[m].y);
                    acc[m].z = fmaf(hv.w, wq3.z, acc[m].z);
                    acc[m].w = fmaf(hv.w, wq3.w, acc[m].w);
                }
            }
            // reduce across the 8 splits (lane bits 2..4)
            #pragma unroll
            for (int m = 0; m < M_ROWS; ++m) {
                #pragma unroll
                for (int o = 4; o <= 16; o <<= 1) {
                    acc[m].x += __shfl_xor_sync(0xffffffffu, acc[m].x, o);
                    acc[m].y += __shfl_xor_sync(0xffffffffu, acc[m].y, o);
                    acc[m].z += __shfl_xor_sync(0xffffffffu, acc[m].z, o);
                    acc[m].w += __shfl_xor_sync(0xffffffffu, acc[m].w, o);
                }
            }
            if (sp == 0) {
                float4 bb = ((const float4*)b2)[q];
                #pragma unroll
                for (int m = 0; m < M_ROWS; ++m)
                    *reinterpret_cast<float4*>(&s_h[m][q * 4]) =
                        make_float4(acc[m].x + bb.x, acc[m].y + bb.y,
                                    acc[m].z + bb.z, acc[m].w + bb.w);
            }
        }
        __syncthreads();

        // ===== Phase D: ect (beta dot) + upd (256 -> 256) j-quads, 8-way k-split ===
        if (wid < M_ROWS) {   // ect[m] = h[m] . beta_w (warps 0..7, one per row)
            int m = wid;
            float p = 0.f;
            for (int k = lane; k < UDIM; k += 32) p = fmaf(s_h[m][k], wbeta[k], p);
            #pragma unroll
            for (int o = 16; o > 0; o >>= 1) p += __shfl_xor_sync(0xffffffffu, p, o);
            if (lane == 0) s_comb[m][UDIM] = p;
        }
        {
            const int q  = (wid << 2) | (lane & 3);   // 0..63
            const int sp = lane >> 2;                 // 0..7
            const int k0 = sp << 5;                   // 32 k per split
            float4 acc[M_ROWS];
            #pragma unroll
            for (int m = 0; m < M_ROWS; ++m) acc[m] = make_float4(0.f, 0.f, 0.f, 0.f);
            #pragma unroll 2
            for (int kk = k0; kk < k0 + 32; kk += 4) {
                float4 wq0 = wuv[(kk + 0) * 64 + q];
                float4 wq1 = wuv[(kk + 1) * 64 + q];
                float4 wq2 = wuv[(kk + 2) * 64 + q];
                float4 wq3 = wuv[(kk + 3) * 64 + q];
                #pragma unroll
                for (int m = 0; m < M_ROWS; ++m) {
                    float4 hv = *reinterpret_cast<const float4*>(&s_h[m][kk]);
                    acc[m].x = fmaf(hv.x, wq0.x, acc[m].x);
                    acc[m].y = fmaf(hv.x, wq0.y, acc[m].y);
                    acc[m].z = fmaf(hv.x, wq0.z, acc[m].z);
                    acc[m].w = fmaf(hv.x, wq0.w, acc[m].w);
                    acc[m].x = fmaf(hv.y, wq1.x, acc[m].x);
                    acc[m].y = fmaf(hv.y, wq1.y, acc[m].y);
                    acc[m].z = fmaf(hv.y, wq1.z, acc[m].z);
                    acc[m].w = fmaf(hv.y, wq1.w, acc[m].w);
                    acc[m].x = fmaf(hv.z, wq2.x, acc[m].x);
                    acc[m].y = fmaf(hv.z, wq2.y, acc[m].y);
                    acc[m].z = fmaf(hv.z, wq2.z, acc[m].z);
                    acc[m].w = fmaf(hv.z, wq2.w, acc[m].w);
                    acc[m].x = fmaf(hv.w, wq3.x, acc[m].x);
                    acc[m].y = fmaf(hv.w, wq3.y, acc[m].y);
                    acc[m].z = fmaf(hv.w, wq3.z, acc[m].z);
                    acc[m].w = fmaf(hv.w, wq3.w, acc[m].w);
                }
            }
            #pragma unroll
            for (int m = 0; m < M_ROWS; ++m) {
                #pragma unroll
                for (int o = 4; o <= 16; o <<= 1) {
                    acc[m].x += __shfl_xor_sync(0xffffffffu, acc[m].x, o);
                    acc[m].y += __shfl_xor_sync(0xffffffffu, acc[m].y, o);
                    acc[m].z += __shfl_xor_sync(0xffffffffu, acc[m].z, o);
                    acc[m].w += __shfl_xor_sync(0xffffffffu, acc[m].w, o);
                }
            }
            if (sp == 0) {
                float4 bb = ((const float4*)bu)[q];
                #pragma unroll
                for (int m = 0; m < M_ROWS; ++m)
                    *reinterpret_cast<float4*>(&s_comb[m][q * 4]) =
                        make_float4(acc[m].x + bb.x, acc[m].y + bb.y,
                                    acc[m].z + bb.z, acc[m].w + bb.w);
            }
        }
        __syncthreads();

        // ================= Phase E: LayerNorm2 over 256 (warps 0..7, one per row) ==
        if (wid < M_ROWS) {
            int m = wid;
            float v[8];
            float4 a = *reinterpret_cast<const float4*>(&s_comb[m][lane * 8]);
            float4 b = *reinterpret_cast<const float4*>(&s_comb[m][lane * 8 + 4]);
            v[0]=a.x; v[1]=a.y; v[2]=a.z; v[3]=a.w;
            v[4]=b.x; v[5]=b.y; v[6]=b.z; v[7]=b.w;
            float sum = 0.f, sq = 0.f;
            #pragma unroll
            for (int q = 0; q < 8; ++q) { sum += v[q]; sq = fmaf(v[q], v[q], sq); }
            #pragma unroll
            for (int o = 16; o > 0; o >>= 1) {
                sum += __shfl_xor_sync(0xffffffffu, sum, o);
                sq  += __shfl_xor_sync(0xffffffffu, sq, o);
            }
            float mean = sum * (1.0f / UDIM);
            float var  = sq * (1.0f / UDIM) - mean * mean;
            float rs = rsqrtf(var + 1e-3f);
            #pragma unroll
            for (int q = 0; q < 8; ++q) {
                int k = lane * 8 + q;
                s_comb[m][k] = (v[q] - mean) * rs * ln2_g[k] + ln2_b[k];
            }
        }
        __syncthreads();

        // ===== Phase F: dec1 (257 -> 512) + tanh, j-quads, 4-way k-split ===========
        {
            const int q  = (wid << 3) | (lane & 7);   // 0..127 (j = 4q..4q+3)
            const int sp = lane >> 3;                 // 0..3 split (lane bits 3..4)
            const int k0 = sp << 6;                   // 64 k per split
            float4 acc[M_ROWS];
            #pragma unroll
            for (int m = 0; m < M_ROWS; ++m) acc[m] = make_float4(0.f, 0.f, 0.f, 0.f);
            #pragma unroll 2
            for (int kk = k0; kk < k0 + 64; kk += 4) {
                float4 wq0 = wd1v[(kk + 0) * 128 + q];
                float4 wq1 = wd1v[(kk + 1) * 128 + q];
                float4 wq2 = wd1v[(kk + 2) * 128 + q];
                float4 wq3 = wd1v[(kk + 3) * 128 + q];
                #pragma unroll
                for (int m = 0; m < M_ROWS; ++m) {
                    float4 cv = *reinterpret_cast<const float4*>(&s_comb[m][kk]);
                    acc[m].x = fmaf(cv.x, wq0.x, acc[m].x);
                    acc[m].y = fmaf(cv.x, wq0.y, acc[m].y);
                    acc[m].z = fmaf(cv.x, wq0.z, acc[m].z);
                    acc[m].w = fmaf(cv.x, wq0.w, acc[m].w);
                    acc[m].x = fmaf(cv.y, wq1.x, acc[m].x);
                    acc[m].y = fmaf(cv.y, wq1.y, acc[m].y);
                    acc[m].z = fmaf(cv.y, wq1.z, acc[m].z);
                    acc[m].w = fmaf(cv.y, wq1.w, acc[m].w);
                    acc[m].x = fmaf(cv.z, wq2.x, acc[m].x);
                    acc[m].y = fmaf(cv.z, wq2.y, acc[m].y);
                    acc[m].z = fmaf(cv.z, wq2.z, acc[m].z);
                    acc[m].w = fmaf(cv.z, wq2.w, acc[m].w);
                    acc[m].x = fmaf(cv.w, wq3.x, acc[m].x);
                    acc[m].y = fmaf(cv.w, wq3.y, acc[m].y);
                    acc[m].z = fmaf(cv.w, wq3.z, acc[m].z);
                    acc[m].w = fmaf(cv.w, wq3.w, acc[m].w);
                }
            }
            if (sp == 3) {   // tail k = 256 (ect column)
                float4 wq = wd1v[256 * 128 + q];
                #pragma unroll
                for (int m = 0; m < M_ROWS; ++m) {
                    float e = s_comb[m][UDIM];
                    acc[m].x = fmaf(e, wq.x, acc[m].x);
                    acc[m].y = fmaf(e, wq.y, acc[m].y);
                    acc[m].z = fmaf(e, wq.z, acc[m].z);
                    acc[m].w = fmaf(e, wq.w, acc[m].w);
                }
            }
            // reduce across the 4 splits (lane bits 3..4)
            #pragma unroll
            for (int m = 0; m < M_ROWS; ++m) {
                #pragma unroll
                for (int o = 8; o <= 16; o <<= 1) {
                    acc[m].x += __shfl_xor_sync(0xffffffffu, acc[m].x, o);
                    acc[m].y += __shfl_xor_sync(0xffffffffu, acc[m].y, o);
                    acc[m].z += __shfl_xor_sync(0xffffffffu, acc[m].z, o);
                    acc[m].w += __shfl_xor_sync(0xffffffffu, acc[m].w, o);
                }
            }
            if (sp == 0) {
                float4 bb = ((const float4*)bd1)[q];
                #pragma unroll
                for (int m = 0; m < M_ROWS; ++m)
                    *reinterpret_cast<float4*>(&s_big[m][q * 4]) =
                        make_float4(tanh_fast(acc[m].x + bb.x), tanh_fast(acc[m].y + bb.y),
                                    tanh_fast(acc[m].z + bb.z), tanh_fast(acc[m].w + bb.w));
            }
        }
        __syncthreads();

        // ===== Phase G: dec2 (512 -> 8), all 16 warps, fix override, output ========
        {
            const int m    = wid & 7;
            const int half = wid >> 3;
            const int n    = lane & 7;
            const int c    = lane >> 3;          // 4 chunks of 64 within the half
            float acc = 0.f;
            const int k0 = half * 256 + c * 64;
            #pragma unroll 4
            for (int k = k0; k < k0 + 64; ++k)
                acc = fmaf(s_big[m][k], wd2[k * NOUT + n], acc);
            acc += __shfl_down_sync(0xffffffffu, acc, 16);
            acc += __shfl_down_sync(0xffffffffu, acc, 8);
            if (half == 1 && lane < 8) s_gp[m][n] = acc;
            __syncthreads();
            if (half == 0 && lane < 8) {
                float y = acc + s_gp[m][n] + bd2[n];
                int b = row0 + m;
                size_t ib = ((size_t)b * S_LEN + (i + 1)) * F_IN;
                if (n == fix0) y = inputs[ib + 1 + fix0];
                if (n == fix1) y = inputs[ib + 1 + fix1];
                s_y[m][n] = y;
                // out shape (NOUT, B, T): out[n, b, t]
                out[(size_t)n * ((size_t)B_TOT * T_OUT) + (size_t)b * T_OUT + (i - LBK)] = y;
            }
        }
        __syncthreads();

        // ---- window shift (each thread owns one (m, n): read-then-write safe)
        if (tid < M_ROWS * NOUT) {
            int m = tid >> 3, n = tid & 7;
            float a = s_win[m][1][n];
            float b = s_win[m][2][n];
            s_win[m][0][n] = a;
            s_win[m][1][n] = b;
            s_win[m][2][n] = s_y[m][n];
        }
        __syncthreads();
    }
}

extern "C" void kernel_launch(void* const* d_in, const int* in_sizes, int n_in,
                              void* d_out, int out_size) {
    const float* inputs = (const float*)d_in[0];
    const float* ln1_g  = (const float*)d_in[1];
    const float* ln1_b  = (const float*)d_in[2];
    const float* w1     = (const float*)d_in[3];
    const float* b1     = (const float*)d_in[4];
    const float* w2     = (const float*)d_in[5];
    const float* b2     = (const float*)d_in[6];
    const float* wu     = (const float*)d_in[7];
    const float* bu     = (const float*)d_in[8];
    const float* ln2_g  = (const float*)d_in[9];
    const float* ln2_b  = (const float*)d_in[10];
    const float* wbeta  = (const float*)d_in[11];
    const float* wd1    = (const float*)d_in[12];
    const float* bd1    = (const float*)d_in[13];
    const float* wd2    = (const float*)d_in[14];
    const float* bd2    = (const float*)d_in[15];
    const int*   fix    = (const int*)  d_in[16];
    float* out = (float*)d_out;

    dps_kernel<<<NCTA, NTHREADS>>>(inputs, ln1_g, ln1_b, w1, b1, w2, b2,
                                   wu, bu, ln2_g, ln2_b, wbeta,
                                   wd1, bd1, wd2, bd2, fix, out);
}